// round 2
// baseline (speedup 1.0000x reference)
#include <cuda_runtime.h>
#include <math.h>

#define H 1024
#define NH 16
#define HD 64
#define SEQ 2048
#define BATCH 2
#define ROWS (BATCH*SEQ)
#define EPSLN 1e-5f

// Scratch (device globals: no allocation allowed)
static __device__ float g_xn[ROWS * H];
static __device__ float g_q[ROWS * H];
static __device__ float g_k[ROWS * H];
static __device__ float g_v[ROWS * H];
static __device__ float g_att[ROWS * H];

// ---------------------------------------------------------------------------
// LayerNorm: one block per row, 256 threads, 1 float4 per thread.
// ---------------------------------------------------------------------------
__global__ void ln_kernel(const float* __restrict__ x,
                          const float* __restrict__ gamma,
                          const float* __restrict__ beta,
                          float* __restrict__ xn) {
    int row = blockIdx.x;
    int t = threadIdx.x;
    float4 v = ((const float4*)(x + (size_t)row * H))[t];
    float s  = v.x + v.y + v.z + v.w;
    float sq = v.x*v.x + v.y*v.y + v.z*v.z + v.w*v.w;

    __shared__ float rs[8], rq[8];
    int lane = t & 31, w = t >> 5;
    #pragma unroll
    for (int o = 16; o; o >>= 1) {
        s  += __shfl_xor_sync(0xffffffffu, s,  o);
        sq += __shfl_xor_sync(0xffffffffu, sq, o);
    }
    if (lane == 0) { rs[w] = s; rq[w] = sq; }
    __syncthreads();
    if (w == 0) {
        float s2  = (lane < 8) ? rs[lane] : 0.f;
        float sq2 = (lane < 8) ? rq[lane] : 0.f;
        #pragma unroll
        for (int o = 4; o; o >>= 1) {
            s2  += __shfl_xor_sync(0xffffffffu, s2,  o);
            sq2 += __shfl_xor_sync(0xffffffffu, sq2, o);
        }
        if (lane == 0) { rs[0] = s2; rq[0] = sq2; }
    }
    __syncthreads();
    float mean = rs[0] * (1.0f / H);
    float var  = rq[0] * (1.0f / H) - mean * mean;
    float rstd = rsqrtf(var + EPSLN);

    float4 g = ((const float4*)gamma)[t];
    float4 b = ((const float4*)beta)[t];
    float4 o4;
    o4.x = (v.x - mean) * rstd * g.x + b.x;
    o4.y = (v.y - mean) * rstd * g.y + b.y;
    o4.z = (v.z - mean) * rstd * g.z + b.z;
    o4.w = (v.w - mean) * rstd * g.w + b.w;
    ((float4*)(xn + (size_t)row * H))[t] = o4;
}

// ---------------------------------------------------------------------------
// GEMM (NT): C[M,N] = A[M,K] * W[N,K]^T     (M=4096, N=1024, K=1024)
// 128x128 block tile, BK=8, 256 threads, 8x8 per thread (split 4+4 mapping).
// mode 0: blockIdx.z picks Wq/Wk/Wv; epilogue writes [B,NH,S,HD] layout.
// mode 1: epilogue adds bias + residual, writes row-major [M,H].
// ---------------------------------------------------------------------------
__global__ __launch_bounds__(256, 2)
void gemm_nt_kernel(const float* __restrict__ A,
                    const float* __restrict__ W0,
                    const float* __restrict__ W1,
                    const float* __restrict__ W2,
                    float* __restrict__ O0,
                    float* __restrict__ O1,
                    float* __restrict__ O2,
                    const float* __restrict__ bias,
                    const float* __restrict__ resid,
                    int mode) {
    const float* Wm = W0;
    float* C = O0;
    if (blockIdx.z == 1) { Wm = W1; C = O1; }
    else if (blockIdx.z == 2) { Wm = W2; C = O2; }

    __shared__ float As[8][128];
    __shared__ float Bs[8][128];

    int tid = threadIdx.x;
    int rowBase = blockIdx.x * 128;
    int colBase = blockIdx.y * 128;

    int lr = tid >> 1;          // 0..127 tile row (A) / tile col (W)
    int lk = (tid & 1) * 4;     // 0 or 4
    const float* aPtr = A  + (size_t)(rowBase + lr) * H + lk;
    const float* bPtr = Wm + (size_t)(colBase + lr) * H + lk;

    int ty = tid >> 4, tx = tid & 15;

    float acc[8][8];
    #pragma unroll
    for (int i = 0; i < 8; i++)
        #pragma unroll
        for (int j = 0; j < 8; j++) acc[i][j] = 0.f;

    for (int k0 = 0; k0 < H; k0 += 8) {
        float4 a4 = *(const float4*)(aPtr + k0);
        float4 b4 = *(const float4*)(bPtr + k0);
        As[lk + 0][lr] = a4.x; As[lk + 1][lr] = a4.y;
        As[lk + 2][lr] = a4.z; As[lk + 3][lr] = a4.w;
        Bs[lk + 0][lr] = b4.x; Bs[lk + 1][lr] = b4.y;
        Bs[lk + 2][lr] = b4.z; Bs[lk + 3][lr] = b4.w;
        __syncthreads();
        #pragma unroll
        for (int kk = 0; kk < 8; kk++) {
            float4 aA = *(const float4*)&As[kk][ty * 4];
            float4 aB = *(const float4*)&As[kk][64 + ty * 4];
            float4 bA = *(const float4*)&Bs[kk][tx * 4];
            float4 bB = *(const float4*)&Bs[kk][64 + tx * 4];
            float ar[8] = {aA.x, aA.y, aA.z, aA.w, aB.x, aB.y, aB.z, aB.w};
            float br[8] = {bA.x, bA.y, bA.z, bA.w, bB.x, bB.y, bB.z, bB.w};
            #pragma unroll
            for (int i = 0; i < 8; i++)
                #pragma unroll
                for (int j = 0; j < 8; j++)
                    acc[i][j] += ar[i] * br[j];
        }
        __syncthreads();
    }

    int rOff[2] = {ty * 4, 64 + ty * 4};
    int cOff[2] = {tx * 4, 64 + tx * 4};

    if (mode == 0) {
        // write to [B, NH, S, HD]
        #pragma unroll
        for (int ri = 0; ri < 2; ri++) {
            #pragma unroll
            for (int i = 0; i < 4; i++) {
                int r = rowBase + rOff[ri] + i;
                int b = r >> 11, sidx = r & 2047;
                #pragma unroll
                for (int cj = 0; cj < 2; cj++) {
                    int c = colBase + cOff[cj];
                    int h = c >> 6, d = c & 63;
                    float4 val;
                    val.x = acc[ri * 4 + i][cj * 4 + 0];
                    val.y = acc[ri * 4 + i][cj * 4 + 1];
                    val.z = acc[ri * 4 + i][cj * 4 + 2];
                    val.w = acc[ri * 4 + i][cj * 4 + 3];
                    size_t idx = (((size_t)(b * NH + h)) * SEQ + sidx) * HD + d;
                    *(float4*)&C[idx] = val;
                }
            }
        }
    } else {
        #pragma unroll
        for (int ri = 0; ri < 2; ri++) {
            #pragma unroll
            for (int i = 0; i < 4; i++) {
                int r = rowBase + rOff[ri] + i;
                #pragma unroll
                for (int cj = 0; cj < 2; cj++) {
                    int c = colBase + cOff[cj];
                    size_t idx = (size_t)r * H + c;
                    float4 res = *(const float4*)&resid[idx];
                    float4 bb = *(const float4*)&bias[c];
                    float4 val;
                    val.x = acc[ri * 4 + i][cj * 4 + 0] + bb.x + res.x;
                    val.y = acc[ri * 4 + i][cj * 4 + 1] + bb.y + res.y;
                    val.z = acc[ri * 4 + i][cj * 4 + 2] + bb.z + res.z;
                    val.w = acc[ri * 4 + i][cj * 4 + 3] + bb.w + res.w;
                    *(float4*)&C[idx] = val;
                }
            }
        }
    }
}

// ---------------------------------------------------------------------------
// Flash attention (fp32): block = (q-tile of 64 rows) x (b,h).
// 256 threads as 16x16, each thread owns 4x4 of the 64x64 S tile and the
// 64x64 O accumulator. KV tile = 64. K tile smem is XOR-swizzled and reused
// for P. All smem static (48KB exactly).
// ---------------------------------------------------------------------------
#define KSW(r, c) ((r) * 64 + ((c) ^ (((r) & 15) << 2)))

__global__ __launch_bounds__(256)
void attn_kernel(const float* __restrict__ Q, const float* __restrict__ K,
                 const float* __restrict__ V, float* __restrict__ Oout) {
    __shared__ float Qs[64 * 64];
    __shared__ float KsP[64 * 64];   // K tile (swizzled), reused for P
    __shared__ float Vs[64 * 64];

    int tid = threadIdx.x;
    int ty = tid >> 4, tx = tid & 15;
    int bh = blockIdx.y;
    int qbase = blockIdx.x * 64;

    const float* Qg = Q + (size_t)bh * SEQ * HD;
    const float* Kg = K + (size_t)bh * SEQ * HD;
    const float* Vg = V + (size_t)bh * SEQ * HD;

    const float scale = 0.125f;  // 1/sqrt(64)

    // load Q tile (scaled)
    #pragma unroll
    for (int i = 0; i < 4; i++) {
        int e = tid + i * 256;
        int r = e >> 4;
        int c = (e & 15) * 4;
        float4 q4 = *(const float4*)&Qg[(size_t)(qbase + r) * HD + c];
        q4.x *= scale; q4.y *= scale; q4.z *= scale; q4.w *= scale;
        *(float4*)&Qs[r * 64 + c] = q4;
    }

    float m[4], l[4], o[4][4];
    #pragma unroll
    for (int i = 0; i < 4; i++) {
        m[i] = -1e30f; l[i] = 0.f;
        #pragma unroll
        for (int j = 0; j < 4; j++) o[i][j] = 0.f;
    }

    for (int j0 = 0; j0 < SEQ; j0 += 64) {
        // load K (swizzled) and V tiles
        #pragma unroll
        for (int i = 0; i < 4; i++) {
            int e = tid + i * 256;
            int r = e >> 4;
            int c = (e & 15) * 4;
            *(float4*)&KsP[KSW(r, c)] = *(const float4*)&Kg[(size_t)(j0 + r) * HD + c];
            *(float4*)&Vs[r * 64 + c]  = *(const float4*)&Vg[(size_t)(j0 + r) * HD + c];
        }
        __syncthreads();

        // S = Q * K^T (rows ty*4+i, cols tx*4+j)
        float sacc[4][4];
        #pragma unroll
        for (int i = 0; i < 4; i++)
            #pragma unroll
            for (int j = 0; j < 4; j++) sacc[i][j] = 0.f;

        #pragma unroll 4
        for (int kk = 0; kk < HD; kk += 4) {
            float4 kf[4];
            #pragma unroll
            for (int j = 0; j < 4; j++)
                kf[j] = *(const float4*)&KsP[KSW(tx * 4 + j, kk)];
            #pragma unroll
            for (int i = 0; i < 4; i++) {
                float4 qv = *(const float4*)&Qs[(ty * 4 + i) * 64 + kk];
                #pragma unroll
                for (int j = 0; j < 4; j++) {
                    sacc[i][j] += qv.x * kf[j].x + qv.y * kf[j].y
                                + qv.z * kf[j].z + qv.w * kf[j].w;
                }
            }
        }

        // online softmax: reduce over tx (16-lane groups)
        float fac[4];
        #pragma unroll
        for (int i = 0; i < 4; i++) {
            float rmax = sacc[i][0];
            #pragma unroll
            for (int j = 1; j < 4; j++) rmax = fmaxf(rmax, sacc[i][j]);
            #pragma unroll
            for (int off = 8; off; off >>= 1)
                rmax = fmaxf(rmax, __shfl_xor_sync(0xffffffffu, rmax, off));
            float mn = fmaxf(m[i], rmax);
            fac[i] = __expf(m[i] - mn);
            m[i] = mn;
            float rsum = 0.f;
            #pragma unroll
            for (int j = 0; j < 4; j++) {
                float p = __expf(sacc[i][j] - mn);
                sacc[i][j] = p;
                rsum += p;
            }
            #pragma unroll
            for (int off = 8; off; off >>= 1)
                rsum += __shfl_xor_sync(0xffffffffu, rsum, off);
            l[i] = l[i] * fac[i] + rsum;
            #pragma unroll
            for (int j = 0; j < 4; j++) o[i][j] *= fac[i];
        }

        __syncthreads();  // everyone done reading K tile

        // write P into KsP (swizzled)
        #pragma unroll
        for (int i = 0; i < 4; i++) {
            float4 p4;
            p4.x = sacc[i][0]; p4.y = sacc[i][1];
            p4.z = sacc[i][2]; p4.w = sacc[i][3];
            *(float4*)&KsP[KSW(ty * 4 + i, tx * 4)] = p4;
        }
        __syncthreads();

        // O += P * V
        #pragma unroll 4
        for (int kv = 0; kv < 64; kv++) {
            float p0 = KsP[KSW(ty * 4 + 0, kv)];
            float p1 = KsP[KSW(ty * 4 + 1, kv)];
            float p2 = KsP[KSW(ty * 4 + 2, kv)];
            float p3 = KsP[KSW(ty * 4 + 3, kv)];
            float4 vv = *(const float4*)&Vs[kv * 64 + tx * 4];
            o[0][0] += p0 * vv.x; o[0][1] += p0 * vv.y; o[0][2] += p0 * vv.z; o[0][3] += p0 * vv.w;
            o[1][0] += p1 * vv.x; o[1][1] += p1 * vv.y; o[1][2] += p1 * vv.z; o[1][3] += p1 * vv.w;
            o[2][0] += p2 * vv.x; o[2][1] += p2 * vv.y; o[2][2] += p2 * vv.z; o[2][3] += p2 * vv.w;
            o[3][0] += p3 * vv.x; o[3][1] += p3 * vv.y; o[3][2] += p3 * vv.z; o[3][3] += p3 * vv.w;
        }
        __syncthreads();
    }

    // finalize: write [B, S, H] layout
    int b = bh >> 4, h = bh & 15;
    #pragma unroll
    for (int i = 0; i < 4; i++) {
        float inv = 1.0f / l[i];
        int r = qbase + ty * 4 + i;
        size_t idx = ((size_t)(b * SEQ + r)) * H + h * HD + tx * 4;
        float4 val;
        val.x = o[i][0] * inv; val.y = o[i][1] * inv;
        val.z = o[i][2] * inv; val.w = o[i][3] * inv;
        *(float4*)&Oout[idx] = val;
    }
}

// ---------------------------------------------------------------------------
extern "C" void kernel_launch(void* const* d_in, const int* in_sizes, int n_in,
                              void* d_out, int out_size) {
    const float* x     = (const float*)d_in[0];
    const float* Wq    = (const float*)d_in[1];
    const float* Wk    = (const float*)d_in[2];
    const float* Wv    = (const float*)d_in[3];
    const float* Wo    = (const float*)d_in[4];
    const float* bo    = (const float*)d_in[5];
    const float* gamma = (const float*)d_in[6];
    const float* beta  = (const float*)d_in[7];
    float* out = (float*)d_out;

    float *xn, *q, *k, *v, *att;
    cudaGetSymbolAddress((void**)&xn,  g_xn);
    cudaGetSymbolAddress((void**)&q,   g_q);
    cudaGetSymbolAddress((void**)&k,   g_k);
    cudaGetSymbolAddress((void**)&v,   g_v);
    cudaGetSymbolAddress((void**)&att, g_att);

    // 1. LayerNorm
    ln_kernel<<<ROWS, 256>>>(x, gamma, beta, xn);

    // 2. QKV projections (one launch, z selects weight/output)
    gemm_nt_kernel<<<dim3(ROWS / 128, H / 128, 3), 256>>>(
        xn, Wq, Wk, Wv, q, k, v, nullptr, nullptr, 0);

    // 3. Attention
    attn_kernel<<<dim3(SEQ / 64, BATCH * NH), 256>>>(q, k, v, att);

    // 4. Output projection + bias + residual
    gemm_nt_kernel<<<dim3(ROWS / 128, H / 128, 1), 256>>>(
        att, Wo, nullptr, nullptr, out, nullptr, nullptr, bo, x, 1);
}

// round 3
// speedup vs baseline: 1.1244x; 1.1244x over previous
#include <cuda_runtime.h>
#include <math.h>
#include <stdint.h>

#define H 1024
#define NH 16
#define HD 64
#define SEQ 2048
#define BATCH 2
#define ROWS (BATCH*SEQ)
#define EPSLN 1e-5f

// Scratch (device globals: no allocation allowed)
static __device__ float g_xn[ROWS * H];
static __device__ float g_q[ROWS * H];
static __device__ float g_k[ROWS * H];
static __device__ float g_v[ROWS * H];
static __device__ float g_att[ROWS * H];

// ---------------------------------------------------------------------------
// LayerNorm: one block per row, 256 threads, 1 float4 per thread.
// ---------------------------------------------------------------------------
__global__ void ln_kernel(const float* __restrict__ x,
                          const float* __restrict__ gamma,
                          const float* __restrict__ beta,
                          float* __restrict__ xn) {
    int row = blockIdx.x;
    int t = threadIdx.x;
    float4 v = ((const float4*)(x + (size_t)row * H))[t];
    float s  = v.x + v.y + v.z + v.w;
    float sq = v.x*v.x + v.y*v.y + v.z*v.z + v.w*v.w;

    __shared__ float rs[8], rq[8];
    int lane = t & 31, w = t >> 5;
    #pragma unroll
    for (int o = 16; o; o >>= 1) {
        s  += __shfl_xor_sync(0xffffffffu, s,  o);
        sq += __shfl_xor_sync(0xffffffffu, sq, o);
    }
    if (lane == 0) { rs[w] = s; rq[w] = sq; }
    __syncthreads();
    if (w == 0) {
        float s2  = (lane < 8) ? rs[lane] : 0.f;
        float sq2 = (lane < 8) ? rq[lane] : 0.f;
        #pragma unroll
        for (int o = 4; o; o >>= 1) {
            s2  += __shfl_xor_sync(0xffffffffu, s2,  o);
            sq2 += __shfl_xor_sync(0xffffffffu, sq2, o);
        }
        if (lane == 0) { rs[0] = s2; rq[0] = sq2; }
    }
    __syncthreads();
    float mean = rs[0] * (1.0f / H);
    float var  = rq[0] * (1.0f / H) - mean * mean;
    float rstd = rsqrtf(var + EPSLN);

    float4 g = ((const float4*)gamma)[t];
    float4 b = ((const float4*)beta)[t];
    float4 o4;
    o4.x = (v.x - mean) * rstd * g.x + b.x;
    o4.y = (v.y - mean) * rstd * g.y + b.y;
    o4.z = (v.z - mean) * rstd * g.z + b.z;
    o4.w = (v.w - mean) * rstd * g.w + b.w;
    ((float4*)(xn + (size_t)row * H))[t] = o4;
}

// ---------------------------------------------------------------------------
// Tensor-core GEMM (NT) via mma.sync m16n8k8 tf32, 3xTF32 split (~fp32 acc).
// C[M,N] = A[M,K] * W[N,K]^T   (M=4096, N=K=1024)
// Block 128x128, BK=8, 256 threads = 8 warps (2m x 4n), warp tile 64x32.
// Producer threads pre-permute gmem data into exact mma fragment order in
// smem ([tile][lane][reg]) so all STS/LDS are .128 and conflict-free.
// mode 0: z selects Wq/Wk/Wv, epilogue writes [B,NH,S,HD].
// mode 1: epilogue adds bias + residual, row-major [M,H].
// ---------------------------------------------------------------------------
__device__ __forceinline__ float tf32_round(float x) {
    uint32_t u;
    asm("cvt.rna.tf32.f32 %0, %1;" : "=r"(u) : "f"(x));
    return __uint_as_float(u);
}

__device__ __forceinline__ void mma_tf32(float* c, uint32_t a0, uint32_t a1,
                                         uint32_t a2, uint32_t a3,
                                         uint32_t b0, uint32_t b1) {
    asm volatile(
        "mma.sync.aligned.m16n8k8.row.col.f32.tf32.tf32.f32 "
        "{%0,%1,%2,%3}, {%4,%5,%6,%7}, {%8,%9}, {%0,%1,%2,%3};\n"
        : "+f"(c[0]), "+f"(c[1]), "+f"(c[2]), "+f"(c[3])
        : "r"(a0), "r"(a1), "r"(a2), "r"(a3), "r"(b0), "r"(b1));
}

__global__ __launch_bounds__(256)
void gemm_tc_kernel(const float* __restrict__ A,
                    const float* __restrict__ W0,
                    const float* __restrict__ W1,
                    const float* __restrict__ W2,
                    float* __restrict__ O0,
                    float* __restrict__ O1,
                    float* __restrict__ O2,
                    const float* __restrict__ bias,
                    const float* __restrict__ resid,
                    int mode) {
    const float* Wm = W0;
    float* C = O0;
    if (blockIdx.z == 1) { Wm = W1; C = O1; }
    else if (blockIdx.z == 2) { Wm = W2; C = O2; }

    // [stage][tile][lane][reg] — fragment-ordered
    __shared__ __align__(16) float As_h[2][8][32][4];
    __shared__ __align__(16) float As_l[2][8][32][4];
    __shared__ __align__(16) float Bs[2][16][32][4];  // {b0h,b1h,b0l,b1l}

    int tid = threadIdx.x;
    int warp = tid >> 5, lane = tid & 31;
    int wm = warp >> 2, wn = warp & 3;
    int g = lane >> 2, t = lane & 3;

    int rowBase = blockIdx.x * 128;
    int colBase = blockIdx.y * 128;

    // ---- producer index precompute ----
    // A: one thread per (mtile, consumer-lane): 256 groups
    int amt = tid >> 5;           // mtile 0..7
    int al  = tid & 31;           // consumer lane
    int ag = al >> 2, at = al & 3;
    const float* aP = A + (size_t)(rowBase + amt * 16 + ag) * H + at;
    // B: two groups per thread: q0 = tid (ntiles 0..7), q1 = tid+256 (8..15)
    int bnt0 = tid >> 5;
    int bl0  = tid & 31;
    int bg0 = bl0 >> 2, bt0 = bl0 & 3;
    const float* bP0 = Wm + (size_t)(colBase + bnt0 * 8 + bg0) * H + bt0;
    int bnt1 = bnt0 + 8;
    const float* bP1 = Wm + (size_t)(colBase + bnt1 * 8 + bg0) * H + bt0;

    float ra[4], rb[4];

    float acc[16][4];
    #pragma unroll
    for (int i = 0; i < 16; i++)
        #pragma unroll
        for (int j = 0; j < 4; j++) acc[i][j] = 0.f;

    // fragment rows: a0=(g,t) a1=(g+8,t) a2=(g,t+4) a3=(g+8,t+4)
    #define FETCH(k0)                                   \
        do {                                            \
            ra[0] = aP[(k0)];                           \
            ra[1] = aP[(k0) + 8 * H];                   \
            ra[2] = aP[(k0) + 4];                       \
            ra[3] = aP[(k0) + 8 * H + 4];               \
            rb[0] = bP0[(k0)];                          \
            rb[1] = bP0[(k0) + 4];                      \
            rb[2] = bP1[(k0)];                          \
            rb[3] = bP1[(k0) + 4];                      \
        } while (0)

    #define STASH(st)                                                        \
        do {                                                                 \
            float4 h4, l4;                                                   \
            h4.x = tf32_round(ra[0]); l4.x = tf32_round(ra[0] - h4.x);       \
            h4.y = tf32_round(ra[1]); l4.y = tf32_round(ra[1] - h4.y);       \
            h4.z = tf32_round(ra[2]); l4.z = tf32_round(ra[2] - h4.z);       \
            h4.w = tf32_round(ra[3]); l4.w = tf32_round(ra[3] - h4.w);       \
            *(float4*)&As_h[st][amt][al][0] = h4;                            \
            *(float4*)&As_l[st][amt][al][0] = l4;                            \
            float4 bb;                                                       \
            bb.x = tf32_round(rb[0]); bb.z = tf32_round(rb[0] - bb.x);       \
            bb.y = tf32_round(rb[1]); bb.w = tf32_round(rb[1] - bb.y);       \
            *(float4*)&Bs[st][bnt0][bl0][0] = bb;                            \
            bb.x = tf32_round(rb[2]); bb.z = tf32_round(rb[2] - bb.x);       \
            bb.y = tf32_round(rb[3]); bb.w = tf32_round(rb[3] - bb.y);       \
            *(float4*)&Bs[st][bnt1][bl0][0] = bb;                            \
        } while (0)

    FETCH(0);
    STASH(0);
    __syncthreads();

    for (int kc = 0; kc < H / 8; kc++) {
        int cur = kc & 1;
        if (kc < H / 8 - 1) FETCH((kc + 1) * 8);

        uint4 Ah[4], Al[4];
        #pragma unroll
        for (int i = 0; i < 4; i++) {
            Ah[i] = *(const uint4*)&As_h[cur][wm * 4 + i][lane][0];
            Al[i] = *(const uint4*)&As_l[cur][wm * 4 + i][lane][0];
        }
        #pragma unroll
        for (int j = 0; j < 4; j++) {
            uint4 B4 = *(const uint4*)&Bs[cur][wn * 4 + j][lane][0];
            #pragma unroll
            for (int i = 0; i < 4; i++) {
                float* c = acc[i * 4 + j];
                mma_tf32(c, Ah[i].x, Ah[i].y, Ah[i].z, Ah[i].w, B4.z, B4.w); // Ah*Bl
                mma_tf32(c, Al[i].x, Al[i].y, Al[i].z, Al[i].w, B4.x, B4.y); // Al*Bh
                mma_tf32(c, Ah[i].x, Ah[i].y, Ah[i].z, Ah[i].w, B4.x, B4.y); // Ah*Bh
            }
        }

        if (kc < H / 8 - 1) STASH(cur ^ 1);
        __syncthreads();
    }

    // ---- epilogue ----
    // c0=(g,2t) c1=(g,2t+1) c2=(g+8,2t) c3=(g+8,2t+1)
    #pragma unroll
    for (int i = 0; i < 4; i++) {
        #pragma unroll
        for (int j = 0; j < 4; j++) {
            float* c = acc[i * 4 + j];
            int r0 = rowBase + wm * 64 + i * 16 + g;
            int col = colBase + wn * 32 + j * 8 + 2 * t;
            if (mode == 0) {
                int b = r0 >> 11, s0 = r0 & 2047;
                int h = col >> 6, d = col & 63;
                size_t base = ((size_t)(b * NH + h)) * SEQ;
                float2 v0 = {c[0], c[1]};
                float2 v1 = {c[2], c[3]};
                *(float2*)&C[(base + s0) * HD + d] = v0;
                *(float2*)&C[(base + s0 + 8) * HD + d] = v1;
            } else {
                size_t i0 = (size_t)r0 * H + col;
                size_t i1 = (size_t)(r0 + 8) * H + col;
                float2 bb = *(const float2*)&bias[col];
                float2 e0 = *(const float2*)&resid[i0];
                float2 e1 = *(const float2*)&resid[i1];
                float2 v0 = {c[0] + bb.x + e0.x, c[1] + bb.y + e0.y};
                float2 v1 = {c[2] + bb.x + e1.x, c[3] + bb.y + e1.y};
                *(float2*)&C[i0] = v0;
                *(float2*)&C[i1] = v1;
            }
        }
    }
    #undef FETCH
    #undef STASH
}

// ---------------------------------------------------------------------------
// Flash attention (fp32): block = (q-tile of 64 rows) x (b,h).
// 256 threads as 16x16, each thread owns 4x4 of the 64x64 S tile and the
// 64x64 O accumulator. KV tile = 64. K tile smem is XOR-swizzled and reused
// for P. All smem static (48KB exactly).
// ---------------------------------------------------------------------------
#define KSW(r, c) ((r) * 64 + ((c) ^ (((r) & 15) << 2)))

__global__ __launch_bounds__(256)
void attn_kernel(const float* __restrict__ Q, const float* __restrict__ K,
                 const float* __restrict__ V, float* __restrict__ Oout) {
    __shared__ float Qs[64 * 64];
    __shared__ float KsP[64 * 64];   // K tile (swizzled), reused for P
    __shared__ float Vs[64 * 64];

    int tid = threadIdx.x;
    int ty = tid >> 4, tx = tid & 15;
    int bh = blockIdx.y;
    int qbase = blockIdx.x * 64;

    const float* Qg = Q + (size_t)bh * SEQ * HD;
    const float* Kg = K + (size_t)bh * SEQ * HD;
    const float* Vg = V + (size_t)bh * SEQ * HD;

    const float scale = 0.125f;  // 1/sqrt(64)

    // load Q tile (scaled)
    #pragma unroll
    for (int i = 0; i < 4; i++) {
        int e = tid + i * 256;
        int r = e >> 4;
        int c = (e & 15) * 4;
        float4 q4 = *(const float4*)&Qg[(size_t)(qbase + r) * HD + c];
        q4.x *= scale; q4.y *= scale; q4.z *= scale; q4.w *= scale;
        *(float4*)&Qs[r * 64 + c] = q4;
    }

    float m[4], l[4], o[4][4];
    #pragma unroll
    for (int i = 0; i < 4; i++) {
        m[i] = -1e30f; l[i] = 0.f;
        #pragma unroll
        for (int j = 0; j < 4; j++) o[i][j] = 0.f;
    }

    for (int j0 = 0; j0 < SEQ; j0 += 64) {
        // load K (swizzled) and V tiles
        #pragma unroll
        for (int i = 0; i < 4; i++) {
            int e = tid + i * 256;
            int r = e >> 4;
            int c = (e & 15) * 4;
            *(float4*)&KsP[KSW(r, c)] = *(const float4*)&Kg[(size_t)(j0 + r) * HD + c];
            *(float4*)&Vs[r * 64 + c]  = *(const float4*)&Vg[(size_t)(j0 + r) * HD + c];
        }
        __syncthreads();

        // S = Q * K^T (rows ty*4+i, cols tx*4+j)
        float sacc[4][4];
        #pragma unroll
        for (int i = 0; i < 4; i++)
            #pragma unroll
            for (int j = 0; j < 4; j++) sacc[i][j] = 0.f;

        #pragma unroll 4
        for (int kk = 0; kk < HD; kk += 4) {
            float4 kf[4];
            #pragma unroll
            for (int j = 0; j < 4; j++)
                kf[j] = *(const float4*)&KsP[KSW(tx * 4 + j, kk)];
            #pragma unroll
            for (int i = 0; i < 4; i++) {
                float4 qv = *(const float4*)&Qs[(ty * 4 + i) * 64 + kk];
                #pragma unroll
                for (int j = 0; j < 4; j++) {
                    sacc[i][j] += qv.x * kf[j].x + qv.y * kf[j].y
                                + qv.z * kf[j].z + qv.w * kf[j].w;
                }
            }
        }

        // online softmax: reduce over tx (16-lane groups)
        float fac[4];
        #pragma unroll
        for (int i = 0; i < 4; i++) {
            float rmax = sacc[i][0];
            #pragma unroll
            for (int j = 1; j < 4; j++) rmax = fmaxf(rmax, sacc[i][j]);
            #pragma unroll
            for (int off = 8; off; off >>= 1)
                rmax = fmaxf(rmax, __shfl_xor_sync(0xffffffffu, rmax, off));
            float mn = fmaxf(m[i], rmax);
            fac[i] = __expf(m[i] - mn);
            m[i] = mn;
            float rsum = 0.f;
            #pragma unroll
            for (int j = 0; j < 4; j++) {
                float p = __expf(sacc[i][j] - mn);
                sacc[i][j] = p;
                rsum += p;
            }
            #pragma unroll
            for (int off = 8; off; off >>= 1)
                rsum += __shfl_xor_sync(0xffffffffu, rsum, off);
            l[i] = l[i] * fac[i] + rsum;
            #pragma unroll
            for (int j = 0; j < 4; j++) o[i][j] *= fac[i];
        }

        __syncthreads();  // everyone done reading K tile

        // write P into KsP (swizzled)
        #pragma unroll
        for (int i = 0; i < 4; i++) {
            float4 p4;
            p4.x = sacc[i][0]; p4.y = sacc[i][1];
            p4.z = sacc[i][2]; p4.w = sacc[i][3];
            *(float4*)&KsP[KSW(ty * 4 + i, tx * 4)] = p4;
        }
        __syncthreads();

        // O += P * V
        #pragma unroll 4
        for (int kv = 0; kv < 64; kv++) {
            float p0 = KsP[KSW(ty * 4 + 0, kv)];
            float p1 = KsP[KSW(ty * 4 + 1, kv)];
            float p2 = KsP[KSW(ty * 4 + 2, kv)];
            float p3 = KsP[KSW(ty * 4 + 3, kv)];
            float4 vv = *(const float4*)&Vs[kv * 64 + tx * 4];
            o[0][0] += p0 * vv.x; o[0][1] += p0 * vv.y; o[0][2] += p0 * vv.z; o[0][3] += p0 * vv.w;
            o[1][0] += p1 * vv.x; o[1][1] += p1 * vv.y; o[1][2] += p1 * vv.z; o[1][3] += p1 * vv.w;
            o[2][0] += p2 * vv.x; o[2][1] += p2 * vv.y; o[2][2] += p2 * vv.z; o[2][3] += p2 * vv.w;
            o[3][0] += p3 * vv.x; o[3][1] += p3 * vv.y; o[3][2] += p3 * vv.z; o[3][3] += p3 * vv.w;
        }
        __syncthreads();
    }

    // finalize: write [B, S, H] layout
    int b = bh >> 4, h = bh & 15;
    #pragma unroll
    for (int i = 0; i < 4; i++) {
        float inv = 1.0f / l[i];
        int r = qbase + ty * 4 + i;
        size_t idx = ((size_t)(b * SEQ + r)) * H + h * HD + tx * 4;
        float4 val;
        val.x = o[i][0] * inv; val.y = o[i][1] * inv;
        val.z = o[i][2] * inv; val.w = o[i][3] * inv;
        *(float4*)&Oout[idx] = val;
    }
}

// ---------------------------------------------------------------------------
extern "C" void kernel_launch(void* const* d_in, const int* in_sizes, int n_in,
                              void* d_out, int out_size) {
    const float* x     = (const float*)d_in[0];
    const float* Wq    = (const float*)d_in[1];
    const float* Wk    = (const float*)d_in[2];
    const float* Wv    = (const float*)d_in[3];
    const float* Wo    = (const float*)d_in[4];
    const float* bo    = (const float*)d_in[5];
    const float* gamma = (const float*)d_in[6];
    const float* beta  = (const float*)d_in[7];
    float* out = (float*)d_out;

    float *xn, *q, *k, *v, *att;
    cudaGetSymbolAddress((void**)&xn,  g_xn);
    cudaGetSymbolAddress((void**)&q,   g_q);
    cudaGetSymbolAddress((void**)&k,   g_k);
    cudaGetSymbolAddress((void**)&v,   g_v);
    cudaGetSymbolAddress((void**)&att, g_att);

    // 1. LayerNorm
    ln_kernel<<<ROWS, 256>>>(x, gamma, beta, xn);

    // 2. QKV projections (one launch, z selects weight/output)
    gemm_tc_kernel<<<dim3(ROWS / 128, H / 128, 3), 256>>>(
        xn, Wq, Wk, Wv, q, k, v, nullptr, nullptr, 0);

    // 3. Attention
    attn_kernel<<<dim3(SEQ / 64, BATCH * NH), 256>>>(q, k, v, att);

    // 4. Output projection + bias + residual
    gemm_tc_kernel<<<dim3(ROWS / 128, H / 128, 1), 256>>>(
        att, Wo, nullptr, nullptr, out, nullptr, nullptr, bo, x, 1);
}

// round 4
// speedup vs baseline: 2.4869x; 2.2118x over previous
#include <cuda_runtime.h>
#include <math.h>
#include <stdint.h>

#define H 1024
#define NH 16
#define HD 64
#define SEQ 2048
#define BATCH 2
#define ROWS (BATCH*SEQ)
#define EPSLN 1e-5f
#define LOG2E 1.44269504f

// Scratch (device globals: no allocation allowed)
static __device__ float g_xn[ROWS * H];
static __device__ float g_q[ROWS * H];
static __device__ float g_k[ROWS * H];
static __device__ float g_v[ROWS * H];
static __device__ float g_att[ROWS * H];

// ---------------------------------------------------------------------------
// LayerNorm: one block per row, 256 threads, 1 float4 per thread.
// ---------------------------------------------------------------------------
__global__ void ln_kernel(const float* __restrict__ x,
                          const float* __restrict__ gamma,
                          const float* __restrict__ beta,
                          float* __restrict__ xn) {
    int row = blockIdx.x;
    int t = threadIdx.x;
    float4 v = ((const float4*)(x + (size_t)row * H))[t];
    float s  = v.x + v.y + v.z + v.w;
    float sq = v.x*v.x + v.y*v.y + v.z*v.z + v.w*v.w;

    __shared__ float rs[8], rq[8];
    int lane = t & 31, w = t >> 5;
    #pragma unroll
    for (int o = 16; o; o >>= 1) {
        s  += __shfl_xor_sync(0xffffffffu, s,  o);
        sq += __shfl_xor_sync(0xffffffffu, sq, o);
    }
    if (lane == 0) { rs[w] = s; rq[w] = sq; }
    __syncthreads();
    if (w == 0) {
        float s2  = (lane < 8) ? rs[lane] : 0.f;
        float sq2 = (lane < 8) ? rq[lane] : 0.f;
        #pragma unroll
        for (int o = 4; o; o >>= 1) {
            s2  += __shfl_xor_sync(0xffffffffu, s2,  o);
            sq2 += __shfl_xor_sync(0xffffffffu, sq2, o);
        }
        if (lane == 0) { rs[0] = s2; rq[0] = sq2; }
    }
    __syncthreads();
    float mean = rs[0] * (1.0f / H);
    float var  = rq[0] * (1.0f / H) - mean * mean;
    float rstd = rsqrtf(var + EPSLN);

    float4 g = ((const float4*)gamma)[t];
    float4 b = ((const float4*)beta)[t];
    float4 o4;
    o4.x = (v.x - mean) * rstd * g.x + b.x;
    o4.y = (v.y - mean) * rstd * g.y + b.y;
    o4.z = (v.z - mean) * rstd * g.z + b.z;
    o4.w = (v.w - mean) * rstd * g.w + b.w;
    ((float4*)(xn + (size_t)row * H))[t] = o4;
}

// ---------------------------------------------------------------------------
// TF32 helpers
// ---------------------------------------------------------------------------
__device__ __forceinline__ float tf32_round(float x) {
    uint32_t u;
    asm("cvt.rna.tf32.f32 %0, %1;" : "=r"(u) : "f"(x));
    return __uint_as_float(u);
}

// D(16x8) += A(16x8) * B(8x8), tf32 operands, fp32 acc.
__device__ __forceinline__ void mma8(float* c, const float* a, float2 b) {
    asm volatile(
        "mma.sync.aligned.m16n8k8.row.col.f32.tf32.tf32.f32 "
        "{%0,%1,%2,%3}, {%4,%5,%6,%7}, {%8,%9}, {%0,%1,%2,%3};\n"
        : "+f"(c[0]), "+f"(c[1]), "+f"(c[2]), "+f"(c[3])
        : "r"(__float_as_uint(a[0])), "r"(__float_as_uint(a[1])),
          "r"(__float_as_uint(a[2])), "r"(__float_as_uint(a[3])),
          "r"(__float_as_uint(b.x)), "r"(__float_as_uint(b.y)));
}

// ---------------------------------------------------------------------------
// Tensor-core GEMM (NT), 2-term TF32 split (A = Ah+Al, B = tf32(B)).
// C[M,N] = A[M,K] * W[N,K]^T   (M=4096, N=K=1024)
// Block 128x128, BK=8, 256 threads = 8 warps (2m x 4n), warp tile 64x32.
// Producer threads pre-permute into exact mma fragment order in smem.
// mode 0: z selects Wq/Wk/Wv, epilogue writes [B,NH,S,HD].
// mode 1: epilogue adds bias + residual, row-major [M,H].
// ---------------------------------------------------------------------------
__global__ __launch_bounds__(256)
void gemm_tc_kernel(const float* __restrict__ A,
                    const float* __restrict__ W0,
                    const float* __restrict__ W1,
                    const float* __restrict__ W2,
                    float* __restrict__ O0,
                    float* __restrict__ O1,
                    float* __restrict__ O2,
                    const float* __restrict__ bias,
                    const float* __restrict__ resid,
                    int mode) {
    const float* Wm = W0;
    float* C = O0;
    if (blockIdx.z == 1) { Wm = W1; C = O1; }
    else if (blockIdx.z == 2) { Wm = W2; C = O2; }

    // [stage][tile][lane][reg] — fragment-ordered
    __shared__ __align__(16) float As_h[2][8][32][4];
    __shared__ __align__(16) float As_l[2][8][32][4];
    __shared__ __align__(16) float Bs[2][16][32][2];  // {b0h,b1h}

    int tid = threadIdx.x;
    int warp = tid >> 5, lane = tid & 31;
    int wm = warp >> 2, wn = warp & 3;
    int g = lane >> 2, t = lane & 3;

    int rowBase = blockIdx.x * 128;
    int colBase = blockIdx.y * 128;

    // ---- producer index precompute ----
    int amt = tid >> 5;           // mtile 0..7
    int al  = tid & 31;           // consumer lane
    int ag = al >> 2, at = al & 3;
    const float* aP = A + (size_t)(rowBase + amt * 16 + ag) * H + at;
    int bnt0 = tid >> 5;
    int bl0  = tid & 31;
    int bg0 = bl0 >> 2, bt0 = bl0 & 3;
    const float* bP0 = Wm + (size_t)(colBase + bnt0 * 8 + bg0) * H + bt0;
    int bnt1 = bnt0 + 8;
    const float* bP1 = Wm + (size_t)(colBase + bnt1 * 8 + bg0) * H + bt0;

    float ra[4], rb[4];

    float acc[16][4];
    #pragma unroll
    for (int i = 0; i < 16; i++)
        #pragma unroll
        for (int j = 0; j < 4; j++) acc[i][j] = 0.f;

    #define FETCH(k0)                                   \
        do {                                            \
            ra[0] = aP[(k0)];                           \
            ra[1] = aP[(k0) + 8 * H];                   \
            ra[2] = aP[(k0) + 4];                       \
            ra[3] = aP[(k0) + 8 * H + 4];               \
            rb[0] = bP0[(k0)];                          \
            rb[1] = bP0[(k0) + 4];                      \
            rb[2] = bP1[(k0)];                          \
            rb[3] = bP1[(k0) + 4];                      \
        } while (0)

    #define STASH(st)                                                        \
        do {                                                                 \
            float4 h4, l4;                                                   \
            h4.x = tf32_round(ra[0]); l4.x = tf32_round(ra[0] - h4.x);       \
            h4.y = tf32_round(ra[1]); l4.y = tf32_round(ra[1] - h4.y);       \
            h4.z = tf32_round(ra[2]); l4.z = tf32_round(ra[2] - h4.z);       \
            h4.w = tf32_round(ra[3]); l4.w = tf32_round(ra[3] - h4.w);       \
            *(float4*)&As_h[st][amt][al][0] = h4;                            \
            *(float4*)&As_l[st][amt][al][0] = l4;                            \
            float2 bb0, bb1;                                                 \
            bb0.x = tf32_round(rb[0]); bb0.y = tf32_round(rb[1]);            \
            bb1.x = tf32_round(rb[2]); bb1.y = tf32_round(rb[3]);            \
            *(float2*)&Bs[st][bnt0][bl0][0] = bb0;                           \
            *(float2*)&Bs[st][bnt1][bl0][0] = bb1;                           \
        } while (0)

    FETCH(0);
    STASH(0);
    __syncthreads();

    for (int kc = 0; kc < H / 8; kc++) {
        int cur = kc & 1;
        if (kc < H / 8 - 1) FETCH((kc + 1) * 8);

        float Ah[4][4], Al[4][4];
        #pragma unroll
        for (int i = 0; i < 4; i++) {
            *(float4*)&Ah[i][0] = *(const float4*)&As_h[cur][wm * 4 + i][lane][0];
            *(float4*)&Al[i][0] = *(const float4*)&As_l[cur][wm * 4 + i][lane][0];
        }
        #pragma unroll
        for (int j = 0; j < 4; j++) {
            float2 B2 = *(const float2*)&Bs[cur][wn * 4 + j][lane][0];
            #pragma unroll
            for (int i = 0; i < 4; i++) {
                mma8(acc[i * 4 + j], Al[i], B2);  // small term first
                mma8(acc[i * 4 + j], Ah[i], B2);
            }
        }

        if (kc < H / 8 - 1) STASH(cur ^ 1);
        __syncthreads();
    }

    // ---- epilogue ----
    #pragma unroll
    for (int i = 0; i < 4; i++) {
        #pragma unroll
        for (int j = 0; j < 4; j++) {
            float* c = acc[i * 4 + j];
            int r0 = rowBase + wm * 64 + i * 16 + g;
            int col = colBase + wn * 32 + j * 8 + 2 * t;
            if (mode == 0) {
                int b = r0 >> 11, s0 = r0 & 2047;
                int h = col >> 6, d = col & 63;
                size_t base = ((size_t)(b * NH + h)) * SEQ;
                float2 v0 = {c[0], c[1]};
                float2 v1 = {c[2], c[3]};
                *(float2*)&C[(base + s0) * HD + d] = v0;
                *(float2*)&C[(base + s0 + 8) * HD + d] = v1;
            } else {
                size_t i0 = (size_t)r0 * H + col;
                size_t i1 = (size_t)(r0 + 8) * H + col;
                float2 bb = *(const float2*)&bias[col];
                float2 e0 = *(const float2*)&resid[i0];
                float2 e1 = *(const float2*)&resid[i1];
                float2 v0 = {c[0] + bb.x + e0.x, c[1] + bb.y + e0.y};
                float2 v1 = {c[2] + bb.x + e1.x, c[3] + bb.y + e1.y};
                *(float2*)&C[i0] = v0;
                *(float2*)&C[i1] = v1;
            }
        }
    }
    #undef FETCH
    #undef STASH
}

// ---------------------------------------------------------------------------
// Tensor-core flash attention (2-term tf32 split on Q and P; K,V tf32).
// Block = 128 q-rows x one (b,h). 256 threads = 8 warps; warp owns 16 rows.
// Q fragments (hi+lo) register-resident across the whole KV loop.
// KV tile = 64. K/V staged fragment-ordered in smem (16KB each).
// P relayout C-frag -> A-frag via warp shuffles (no smem round trip).
// exp in base-2 domain (Q pre-scaled by 0.125*log2e).
// ---------------------------------------------------------------------------
__global__ __launch_bounds__(256)
void attn_tc_kernel(const float* __restrict__ Q, const float* __restrict__ K,
                    const float* __restrict__ V, float* __restrict__ Oout) {
    __shared__ __align__(16) float Ks[8][8][32][2];  // [kc=HD][nt=kv][lane][{b0,b1}]
    __shared__ __align__(16) float Vs[8][8][32][2];  // [kc=kv][nt=HD][lane][{b0,b1}]

    int tid = threadIdx.x;
    int warp = tid >> 5, lane = tid & 31;
    int g = lane >> 2, t = lane & 3;
    int bh = blockIdx.y;
    int qbase = blockIdx.x * 128;
    int qrow0 = qbase + warp * 16;

    const float* Qg = Q + (size_t)bh * SEQ * HD;
    const float* Kg = K + (size_t)bh * SEQ * HD;
    const float* Vg = V + (size_t)bh * SEQ * HD;

    const float sc = 0.125f * LOG2E;

    // ---- Q fragments: [kchunk][4], split hi/lo ----
    float qh[8][4], ql[8][4];
    {
        const float* q0 = Qg + (size_t)(qrow0 + g) * HD;
        const float* q1 = Qg + (size_t)(qrow0 + g + 8) * HD;
        #pragma unroll
        for (int c = 0; c < 8; c++) {
            float a0 = q0[8 * c + t]     * sc;
            float a1 = q1[8 * c + t]     * sc;
            float a2 = q0[8 * c + t + 4] * sc;
            float a3 = q1[8 * c + t + 4] * sc;
            qh[c][0] = tf32_round(a0); ql[c][0] = tf32_round(a0 - qh[c][0]);
            qh[c][1] = tf32_round(a1); ql[c][1] = tf32_round(a1 - qh[c][1]);
            qh[c][2] = tf32_round(a2); ql[c][2] = tf32_round(a2 - qh[c][2]);
            qh[c][3] = tf32_round(a3); ql[c][3] = tf32_round(a3 - qh[c][3]);
        }
    }

    float m0 = -1e30f, m1 = -1e30f, l0 = 0.f, l1 = 0.f;
    float o[8][4];
    #pragma unroll
    for (int j = 0; j < 8; j++)
        #pragma unroll
        for (int r = 0; r < 4; r++) o[j][r] = 0.f;

    int src_lo = (lane & 28) | (t >> 1);
    int src_hi = src_lo + 2;
    bool odd = (t & 1);

    for (int kv0 = 0; kv0 < SEQ; kv0 += 64) {
        // ---- producers: fragment-ordered K and V (all 256 threads) ----
        {
            int j = warp;  // ntile index this thread serves
            const float* kr = Kg + (size_t)(kv0 + 8 * j + g) * HD;
            #pragma unroll
            for (int c = 0; c < 8; c++) {
                float2 b;
                b.x = tf32_round(kr[8 * c + t]);
                b.y = tf32_round(kr[8 * c + t + 4]);
                *(float2*)&Ks[c][j][lane][0] = b;
            }
            const float* vb = Vg + (size_t)kv0 * HD + 8 * j + g;
            #pragma unroll
            for (int c = 0; c < 8; c++) {
                float2 b;
                b.x = tf32_round(vb[(8 * c + t) * HD]);
                b.y = tf32_round(vb[(8 * c + t + 4) * HD]);
                *(float2*)&Vs[c][j][lane][0] = b;
            }
        }
        __syncthreads();

        // ---- S = Q * K^T ----
        float sacc[8][4];
        #pragma unroll
        for (int j = 0; j < 8; j++)
            #pragma unroll
            for (int r = 0; r < 4; r++) sacc[j][r] = 0.f;

        #pragma unroll
        for (int c = 0; c < 8; c++) {
            #pragma unroll
            for (int j = 0; j < 8; j++) {
                float2 b = *(const float2*)&Ks[c][j][lane][0];
                mma8(sacc[j], ql[c], b);
                mma8(sacc[j], qh[c], b);
            }
        }

        // ---- online softmax (base-2) ----
        float mx0 = -1e30f, mx1 = -1e30f;
        #pragma unroll
        for (int j = 0; j < 8; j++) {
            mx0 = fmaxf(mx0, fmaxf(sacc[j][0], sacc[j][1]));
            mx1 = fmaxf(mx1, fmaxf(sacc[j][2], sacc[j][3]));
        }
        mx0 = fmaxf(mx0, __shfl_xor_sync(0xffffffffu, mx0, 1));
        mx0 = fmaxf(mx0, __shfl_xor_sync(0xffffffffu, mx0, 2));
        mx1 = fmaxf(mx1, __shfl_xor_sync(0xffffffffu, mx1, 1));
        mx1 = fmaxf(mx1, __shfl_xor_sync(0xffffffffu, mx1, 2));
        float nm0 = fmaxf(m0, mx0), nm1 = fmaxf(m1, mx1);
        float f0 = exp2f(m0 - nm0), f1 = exp2f(m1 - nm1);
        m0 = nm0; m1 = nm1;
        float s0 = 0.f, s1 = 0.f;
        #pragma unroll
        for (int j = 0; j < 8; j++) {
            sacc[j][0] = exp2f(sacc[j][0] - nm0); s0 += sacc[j][0];
            sacc[j][1] = exp2f(sacc[j][1] - nm0); s0 += sacc[j][1];
            sacc[j][2] = exp2f(sacc[j][2] - nm1); s1 += sacc[j][2];
            sacc[j][3] = exp2f(sacc[j][3] - nm1); s1 += sacc[j][3];
        }
        s0 += __shfl_xor_sync(0xffffffffu, s0, 1);
        s0 += __shfl_xor_sync(0xffffffffu, s0, 2);
        s1 += __shfl_xor_sync(0xffffffffu, s1, 1);
        s1 += __shfl_xor_sync(0xffffffffu, s1, 2);
        l0 = l0 * f0 + s0;
        l1 = l1 * f1 + s1;
        #pragma unroll
        for (int j = 0; j < 8; j++) {
            o[j][0] *= f0; o[j][1] *= f0;
            o[j][2] *= f1; o[j][3] *= f1;
        }

        // ---- O += P * V  (P: C-frag -> A-frag via shuffles, split hi/lo) ----
        #pragma unroll
        for (int c = 0; c < 8; c++) {
            float v00 = __shfl_sync(0xffffffffu, sacc[c][0], src_lo);
            float v01 = __shfl_sync(0xffffffffu, sacc[c][1], src_lo);
            float v20 = __shfl_sync(0xffffffffu, sacc[c][2], src_lo);
            float v21 = __shfl_sync(0xffffffffu, sacc[c][3], src_lo);
            float w00 = __shfl_sync(0xffffffffu, sacc[c][0], src_hi);
            float w01 = __shfl_sync(0xffffffffu, sacc[c][1], src_hi);
            float w20 = __shfl_sync(0xffffffffu, sacc[c][2], src_hi);
            float w21 = __shfl_sync(0xffffffffu, sacc[c][3], src_hi);
            float pa0 = odd ? v01 : v00;   // (g,    kv 8c+t)
            float pa1 = odd ? v21 : v20;   // (g+8,  kv 8c+t)
            float pa2 = odd ? w01 : w00;   // (g,    kv 8c+t+4)
            float pa3 = odd ? w21 : w20;   // (g+8,  kv 8c+t+4)
            float ph[4], pl[4];
            ph[0] = tf32_round(pa0); pl[0] = tf32_round(pa0 - ph[0]);
            ph[1] = tf32_round(pa1); pl[1] = tf32_round(pa1 - ph[1]);
            ph[2] = tf32_round(pa2); pl[2] = tf32_round(pa2 - ph[2]);
            ph[3] = tf32_round(pa3); pl[3] = tf32_round(pa3 - ph[3]);
            #pragma unroll
            for (int j = 0; j < 8; j++) {
                float2 b = *(const float2*)&Vs[c][j][lane][0];
                mma8(o[j], pl, b);
                mma8(o[j], ph, b);
            }
        }
        __syncthreads();
    }

    // ---- finalize: write [B, S, H] ----
    int b = bh >> 4, h = bh & 15;
    float inv0 = 1.0f / l0, inv1 = 1.0f / l1;
    int r0 = qrow0 + g, r1 = r0 + 8;
    #pragma unroll
    for (int j = 0; j < 8; j++) {
        int col = h * HD + 8 * j + 2 * t;
        float2 v0 = {o[j][0] * inv0, o[j][1] * inv0};
        float2 v1 = {o[j][2] * inv1, o[j][3] * inv1};
        *(float2*)&Oout[((size_t)(b * SEQ + r0)) * H + col] = v0;
        *(float2*)&Oout[((size_t)(b * SEQ + r1)) * H + col] = v1;
    }
}

// ---------------------------------------------------------------------------
extern "C" void kernel_launch(void* const* d_in, const int* in_sizes, int n_in,
                              void* d_out, int out_size) {
    const float* x     = (const float*)d_in[0];
    const float* Wq    = (const float*)d_in[1];
    const float* Wk    = (const float*)d_in[2];
    const float* Wv    = (const float*)d_in[3];
    const float* Wo    = (const float*)d_in[4];
    const float* bo    = (const float*)d_in[5];
    const float* gamma = (const float*)d_in[6];
    const float* beta  = (const float*)d_in[7];
    float* out = (float*)d_out;

    float *xn, *q, *k, *v, *att;
    cudaGetSymbolAddress((void**)&xn,  g_xn);
    cudaGetSymbolAddress((void**)&q,   g_q);
    cudaGetSymbolAddress((void**)&k,   g_k);
    cudaGetSymbolAddress((void**)&v,   g_v);
    cudaGetSymbolAddress((void**)&att, g_att);

    // 1. LayerNorm
    ln_kernel<<<ROWS, 256>>>(x, gamma, beta, xn);

    // 2. QKV projections (one launch, z selects weight/output)
    gemm_tc_kernel<<<dim3(ROWS / 128, H / 128, 3), 256>>>(
        xn, Wq, Wk, Wv, q, k, v, nullptr, nullptr, 0);

    // 3. Attention (tensor-core flash)
    attn_tc_kernel<<<dim3(SEQ / 128, BATCH * NH), 256>>>(q, k, v, att);

    // 4. Output projection + bias + residual
    gemm_tc_kernel<<<dim3(ROWS / 128, H / 128, 1), 256>>>(
        att, Wo, nullptr, nullptr, out, nullptr, nullptr, bo, x, 1);
}

// round 6
// speedup vs baseline: 3.8080x; 1.5312x over previous
#include <cuda_runtime.h>
#include <cuda_bf16.h>
#include <math.h>
#include <stdint.h>

#define H 1024
#define NH 16
#define HD 64
#define SEQ 2048
#define BATCH 2
#define ROWS (BATCH*SEQ)
#define EPSLN 1e-5f
#define LOG2E 1.44269504f

// ---------------- scratch (device globals; no allocation allowed) ----------
static __device__ __nv_bfloat16 g_xnh[ROWS * H];   // LN out hi
static __device__ __nv_bfloat16 g_xnl[ROWS * H];   // LN out lo
static __device__ __nv_bfloat16 g_wh[4 * H * H];   // weights hi (q,k,v,o)
static __device__ __nv_bfloat16 g_qh[ROWS * H];
static __device__ __nv_bfloat16 g_ql[ROWS * H];
static __device__ __nv_bfloat16 g_kh[ROWS * H];
static __device__ __nv_bfloat16 g_vh[ROWS * H];
static __device__ __nv_bfloat16 g_ath[ROWS * H];
static __device__ __nv_bfloat16 g_atl[ROWS * H];

// ---------------- helpers --------------------------------------------------
// D(16x8,f32) += A(16x16 bf16) * B(16x8 bf16)
__device__ __forceinline__ void mmabf(float* c, uint4 a, uint2 b) {
    asm volatile(
        "mma.sync.aligned.m16n8k16.row.col.f32.bf16.bf16.f32 "
        "{%0,%1,%2,%3}, {%4,%5,%6,%7}, {%8,%9}, {%0,%1,%2,%3};\n"
        : "+f"(c[0]), "+f"(c[1]), "+f"(c[2]), "+f"(c[3])
        : "r"(a.x), "r"(a.y), "r"(a.z), "r"(a.w), "r"(b.x), "r"(b.y));
}

__device__ __forceinline__ uint32_t pkbf(float a, float b) {
    __nv_bfloat162 h;
    h.x = __float2bfloat16_rn(a);
    h.y = __float2bfloat16_rn(b);
    return *reinterpret_cast<uint32_t*>(&h);
}
// hi = bf16 pair of (a,b); lo = bf16 pair of residuals
__device__ __forceinline__ uint32_t pksplit(float a, float b, uint32_t* lo) {
    __nv_bfloat16 ha = __float2bfloat16_rn(a);
    __nv_bfloat16 hb = __float2bfloat16_rn(b);
    __nv_bfloat162 l2;
    l2.x = __float2bfloat16_rn(a - __bfloat162float(ha));
    l2.y = __float2bfloat16_rn(b - __bfloat162float(hb));
    *lo = *reinterpret_cast<uint32_t*>(&l2);
    __nv_bfloat162 h2; h2.x = ha; h2.y = hb;
    return *reinterpret_cast<uint32_t*>(&h2);
}

// ---------------------------------------------------------------------------
// LayerNorm -> bf16 hi/lo
// ---------------------------------------------------------------------------
__global__ void ln_kernel(const float* __restrict__ x,
                          const float* __restrict__ gamma,
                          const float* __restrict__ beta,
                          __nv_bfloat16* __restrict__ xnh,
                          __nv_bfloat16* __restrict__ xnl) {
    int row = blockIdx.x;
    int t = threadIdx.x;
    float4 v = ((const float4*)(x + (size_t)row * H))[t];
    float s  = v.x + v.y + v.z + v.w;
    float sq = v.x*v.x + v.y*v.y + v.z*v.z + v.w*v.w;

    __shared__ float rs[8], rq[8];
    int lane = t & 31, w = t >> 5;
    #pragma unroll
    for (int o = 16; o; o >>= 1) {
        s  += __shfl_xor_sync(0xffffffffu, s,  o);
        sq += __shfl_xor_sync(0xffffffffu, sq, o);
    }
    if (lane == 0) { rs[w] = s; rq[w] = sq; }
    __syncthreads();
    if (w == 0) {
        float s2  = (lane < 8) ? rs[lane] : 0.f;
        float sq2 = (lane < 8) ? rq[lane] : 0.f;
        #pragma unroll
        for (int o = 4; o; o >>= 1) {
            s2  += __shfl_xor_sync(0xffffffffu, s2,  o);
            sq2 += __shfl_xor_sync(0xffffffffu, sq2, o);
        }
        if (lane == 0) { rs[0] = s2; rq[0] = sq2; }
    }
    __syncthreads();
    float mean = rs[0] * (1.0f / H);
    float var  = rq[0] * (1.0f / H) - mean * mean;
    float rstd = rsqrtf(var + EPSLN);

    float4 g = ((const float4*)gamma)[t];
    float4 b = ((const float4*)beta)[t];
    float y0 = (v.x - mean) * rstd * g.x + b.x;
    float y1 = (v.y - mean) * rstd * g.y + b.y;
    float y2 = (v.z - mean) * rstd * g.z + b.z;
    float y3 = (v.w - mean) * rstd * g.w + b.w;
    uint32_t lo0, lo1;
    uint32_t hi0 = pksplit(y0, y1, &lo0);
    uint32_t hi1 = pksplit(y2, y3, &lo1);
    size_t o = (size_t)row * H + 4 * t;
    *(uint2*)&xnh[o] = make_uint2(hi0, hi1);
    *(uint2*)&xnl[o] = make_uint2(lo0, lo1);
}

// ---------------------------------------------------------------------------
// Weight convert: 4 fp32 matrices -> bf16 (hi only; B-side operand)
// ---------------------------------------------------------------------------
__global__ void wsplit_kernel(const float* __restrict__ Wq, const float* __restrict__ Wk,
                              const float* __restrict__ Wv, const float* __restrict__ Wo,
                              __nv_bfloat16* __restrict__ wh) {
    int gid = blockIdx.x * blockDim.x + threadIdx.x;
    int m = gid >> 18;
    size_t off = (size_t)(gid & 0x3FFFF) * 4;
    const float* src = (m == 0) ? Wq : (m == 1) ? Wk : (m == 2) ? Wv : Wo;
    float4 v = *(const float4*)(src + off);
    uint32_t h0 = pkbf(v.x, v.y);
    uint32_t h1 = pkbf(v.z, v.w);
    *(uint2*)&wh[(size_t)m * H * H + off] = make_uint2(h0, h1);
}

// ---------------------------------------------------------------------------
// bf16 GEMM (NT): C[4096,1024] = (Ah+Al)[M,K] * Wh[N,K]^T, fp32 acc.
// mma.m16n8k16 bf16, 2-term split. Block 128x128, BK=16, 8 warps (2m x 4n).
// Fragment-ordered smem, double-buffered.
// mode 0: z selects output: z=0 -> qh+ql, z=1 -> kh, z=2 -> vh  ([B,NH,S,HD])
// mode 1: out = C + bias + resid (fp32 row-major)
// ---------------------------------------------------------------------------
__global__ __launch_bounds__(256)
void gemm_bf16_kernel(const __nv_bfloat16* __restrict__ Ah,
                      const __nv_bfloat16* __restrict__ Al,
                      const __nv_bfloat16* __restrict__ Wall,
                      __nv_bfloat16* __restrict__ qh, __nv_bfloat16* __restrict__ ql,
                      __nv_bfloat16* __restrict__ kh, __nv_bfloat16* __restrict__ vh,
                      float* __restrict__ out, const float* __restrict__ bias,
                      const float* __restrict__ resid, int mode) {
    const __nv_bfloat16* Wh = Wall + (size_t)blockIdx.z * H * H;

    __shared__ __align__(16) uint32_t As_h[2][8][32][4];
    __shared__ __align__(16) uint32_t As_l[2][8][32][4];
    __shared__ __align__(16) uint32_t Bs[2][16][32][2];

    int tid = threadIdx.x;
    int warp = tid >> 5, lane = tid & 31;
    int wm = warp >> 2, wn = warp & 3;
    int g = lane >> 2, t = lane & 3;

    int rowBase = blockIdx.x * 128;
    int colBase = blockIdx.y * 128;

    // producers
    int amt = tid >> 5, al = tid & 31;
    int ag = al >> 2, at = al & 3;
    size_t arow_g  = (size_t)(rowBase + amt * 16 + ag) * H;
    size_t arow_g8 = arow_g + 8 * H;
    int ac0 = 2 * at, ac1 = 2 * at + 8;

    int bnt = tid >> 5, bl = tid & 31;
    int bg = bl >> 2, bt = bl & 3;
    size_t brow0 = (size_t)(colBase + bnt * 8 + bg) * H;
    size_t brow1 = brow0 + 64 * H;
    int bc0 = 2 * bt, bc1 = 2 * bt + 8;

    uint32_t ha[4], la[4], hb[4];

    float acc[16][4];
    #pragma unroll
    for (int i = 0; i < 16; i++)
        #pragma unroll
        for (int j = 0; j < 4; j++) acc[i][j] = 0.f;

    #define FETCH(k0)                                            \
        do {                                                     \
            ha[0] = *(const uint32_t*)&Ah[arow_g  + (k0) + ac0]; \
            ha[1] = *(const uint32_t*)&Ah[arow_g8 + (k0) + ac0]; \
            ha[2] = *(const uint32_t*)&Ah[arow_g  + (k0) + ac1]; \
            ha[3] = *(const uint32_t*)&Ah[arow_g8 + (k0) + ac1]; \
            la[0] = *(const uint32_t*)&Al[arow_g  + (k0) + ac0]; \
            la[1] = *(const uint32_t*)&Al[arow_g8 + (k0) + ac0]; \
            la[2] = *(const uint32_t*)&Al[arow_g  + (k0) + ac1]; \
            la[3] = *(const uint32_t*)&Al[arow_g8 + (k0) + ac1]; \
            hb[0] = *(const uint32_t*)&Wh[brow0 + (k0) + bc0];   \
            hb[1] = *(const uint32_t*)&Wh[brow0 + (k0) + bc1];   \
            hb[2] = *(const uint32_t*)&Wh[brow1 + (k0) + bc0];   \
            hb[3] = *(const uint32_t*)&Wh[brow1 + (k0) + bc1];   \
        } while (0)

    #define STASH(st)                                                          \
        do {                                                                   \
            *(uint4*)&As_h[st][amt][al][0] = make_uint4(ha[0], ha[1], ha[2], ha[3]); \
            *(uint4*)&As_l[st][amt][al][0] = make_uint4(la[0], la[1], la[2], la[3]); \
            *(uint2*)&Bs[st][bnt][bl][0]     = make_uint2(hb[0], hb[1]);       \
            *(uint2*)&Bs[st][bnt + 8][bl][0] = make_uint2(hb[2], hb[3]);       \
        } while (0)

    FETCH(0);
    STASH(0);
    __syncthreads();

    for (int kc = 0; kc < H / 16; kc++) {
        int cur = kc & 1;
        if (kc < H / 16 - 1) FETCH((kc + 1) * 16);

        uint4 A_h[4], A_l[4];
        #pragma unroll
        for (int i = 0; i < 4; i++) {
            A_h[i] = *(const uint4*)&As_h[cur][wm * 4 + i][lane][0];
            A_l[i] = *(const uint4*)&As_l[cur][wm * 4 + i][lane][0];
        }
        #pragma unroll
        for (int j = 0; j < 4; j++) {
            uint2 B2 = *(const uint2*)&Bs[cur][wn * 4 + j][lane][0];
            #pragma unroll
            for (int i = 0; i < 4; i++) {
                mmabf(acc[i * 4 + j], A_l[i], B2);
                mmabf(acc[i * 4 + j], A_h[i], B2);
            }
        }

        if (kc < H / 16 - 1) STASH(cur ^ 1);
        __syncthreads();
    }

    // ---- epilogue: c0=(g,2t) c1=(g,2t+1) c2=(g+8,2t) c3=(g+8,2t+1) ----
    #pragma unroll
    for (int i = 0; i < 4; i++) {
        #pragma unroll
        for (int j = 0; j < 4; j++) {
            float* c = acc[i * 4 + j];
            int r0 = rowBase + wm * 64 + i * 16 + g;
            int col = colBase + wn * 32 + j * 8 + 2 * t;
            if (mode == 0) {
                int b = r0 >> 11, s = r0 & 2047;
                int hh = col >> 6, d = col & 63;
                size_t i0 = (((size_t)(b * NH + hh)) * SEQ + s) * HD + d;
                size_t i1 = i0 + 8 * HD;
                if (blockIdx.z == 0) {
                    uint32_t lo0, lo1;
                    uint32_t hi0 = pksplit(c[0], c[1], &lo0);
                    uint32_t hi1 = pksplit(c[2], c[3], &lo1);
                    *(uint32_t*)&qh[i0] = hi0; *(uint32_t*)&ql[i0] = lo0;
                    *(uint32_t*)&qh[i1] = hi1; *(uint32_t*)&ql[i1] = lo1;
                } else if (blockIdx.z == 1) {
                    *(uint32_t*)&kh[i0] = pkbf(c[0], c[1]);
                    *(uint32_t*)&kh[i1] = pkbf(c[2], c[3]);
                } else {
                    *(uint32_t*)&vh[i0] = pkbf(c[0], c[1]);
                    *(uint32_t*)&vh[i1] = pkbf(c[2], c[3]);
                }
            } else {
                size_t i0 = (size_t)r0 * H + col;
                size_t i1 = i0 + 8 * H;
                float2 bb = *(const float2*)&bias[col];
                float2 e0 = *(const float2*)&resid[i0];
                float2 e1 = *(const float2*)&resid[i1];
                float2 v0 = {c[0] + bb.x + e0.x, c[1] + bb.y + e0.y};
                float2 v1 = {c[2] + bb.x + e1.x, c[3] + bb.y + e1.y};
                *(float2*)&out[i0] = v0;
                *(float2*)&out[i1] = v1;
            }
        }
    }
    #undef FETCH
    #undef STASH
}

// ---------------------------------------------------------------------------
// bf16 flash attention. Block = 128 q-rows x one (b,h), 8 warps x 16 rows.
// S = (Qh+Ql)*Kh^T (2 mma/k16); softmax base-2; O += (Ph+Pl)*Vh.
// C-frag -> A-frag for P is the identity for k16 bf16 fragments (no shuffles).
// Scale applied post-mma in fp32.
// ---------------------------------------------------------------------------
__global__ __launch_bounds__(256)
void attn_bf16_kernel(const __nv_bfloat16* __restrict__ Qh,
                      const __nv_bfloat16* __restrict__ Ql,
                      const __nv_bfloat16* __restrict__ Kh,
                      const __nv_bfloat16* __restrict__ Vh,
                      __nv_bfloat16* __restrict__ ath,
                      __nv_bfloat16* __restrict__ atl) {
    __shared__ __align__(16) uint32_t Ks[4][8][32][2];
    __shared__ __align__(16) uint32_t Vs[4][8][32][2];

    int tid = threadIdx.x;
    int warp = tid >> 5, lane = tid & 31;
    int g = lane >> 2, t = lane & 3;
    int bh = blockIdx.y;
    int qrow0 = blockIdx.x * 128 + warp * 16;

    const float sc2 = 0.125f * LOG2E;

    // Q fragments (register-resident)
    uint4 qAh[4], qAl[4];
    {
        size_t qo_g  = ((size_t)bh * SEQ + qrow0 + g) * HD;
        size_t qo_g8 = qo_g + 8 * HD;
        #pragma unroll
        for (int c = 0; c < 4; c++) {
            int c0 = 16 * c + 2 * t, c1 = c0 + 8;
            qAh[c] = make_uint4(*(const uint32_t*)&Qh[qo_g + c0],
                                *(const uint32_t*)&Qh[qo_g8 + c0],
                                *(const uint32_t*)&Qh[qo_g + c1],
                                *(const uint32_t*)&Qh[qo_g8 + c1]);
            qAl[c] = make_uint4(*(const uint32_t*)&Ql[qo_g + c0],
                                *(const uint32_t*)&Ql[qo_g8 + c0],
                                *(const uint32_t*)&Ql[qo_g + c1],
                                *(const uint32_t*)&Ql[qo_g8 + c1]);
        }
    }

    float m0 = -1e30f, m1 = -1e30f, l0 = 0.f, l1 = 0.f;
    float o[8][4];
    #pragma unroll
    for (int j = 0; j < 8; j++)
        #pragma unroll
        for (int r = 0; r < 4; r++) o[j][r] = 0.f;

    for (int kv0 = 0; kv0 < SEQ; kv0 += 64) {
        // ---- producers: warp j fills ntile j of K and V ----
        {
            int j = warp;
            const __nv_bfloat16* kr = Kh + ((size_t)bh * SEQ + kv0 + 8 * j + g) * HD;
            #pragma unroll
            for (int c = 0; c < 4; c++) {
                Ks[c][j][lane][0] = *(const uint32_t*)&kr[16 * c + 2 * t];
                Ks[c][j][lane][1] = *(const uint32_t*)&kr[16 * c + 2 * t + 8];
            }
            const __nv_bfloat16* vb = Vh + ((size_t)bh * SEQ + kv0) * HD + 8 * j + g;
            #pragma unroll
            for (int c = 0; c < 4; c++) {
                int r0 = 16 * c + 2 * t;
                __nv_bfloat162 p01, p23;
                p01.x = vb[(size_t)r0 * HD];
                p01.y = vb[(size_t)(r0 + 1) * HD];
                p23.x = vb[(size_t)(r0 + 8) * HD];
                p23.y = vb[(size_t)(r0 + 9) * HD];
                Vs[c][j][lane][0] = *reinterpret_cast<uint32_t*>(&p01);
                Vs[c][j][lane][1] = *reinterpret_cast<uint32_t*>(&p23);
            }
        }
        __syncthreads();

        // ---- S = Q * K^T ----
        float sacc[8][4];
        #pragma unroll
        for (int j = 0; j < 8; j++)
            #pragma unroll
            for (int r = 0; r < 4; r++) sacc[j][r] = 0.f;

        #pragma unroll
        for (int c = 0; c < 4; c++) {
            #pragma unroll
            for (int j = 0; j < 8; j++) {
                uint2 kb = *(const uint2*)&Ks[c][j][lane][0];
                mmabf(sacc[j], qAl[c], kb);
                mmabf(sacc[j], qAh[c], kb);
            }
        }
        #pragma unroll
        for (int j = 0; j < 8; j++) {
            sacc[j][0] *= sc2; sacc[j][1] *= sc2;
            sacc[j][2] *= sc2; sacc[j][3] *= sc2;
        }

        // ---- online softmax (rows g: c0,c1 | rows g+8: c2,c3) ----
        float mx0 = -1e30f, mx1 = -1e30f;
        #pragma unroll
        for (int j = 0; j < 8; j++) {
            mx0 = fmaxf(mx0, fmaxf(sacc[j][0], sacc[j][1]));
            mx1 = fmaxf(mx1, fmaxf(sacc[j][2], sacc[j][3]));
        }
        mx0 = fmaxf(mx0, __shfl_xor_sync(0xffffffffu, mx0, 1));
        mx0 = fmaxf(mx0, __shfl_xor_sync(0xffffffffu, mx0, 2));
        mx1 = fmaxf(mx1, __shfl_xor_sync(0xffffffffu, mx1, 1));
        mx1 = fmaxf(mx1, __shfl_xor_sync(0xffffffffu, mx1, 2));
        float nm0 = fmaxf(m0, mx0), nm1 = fmaxf(m1, mx1);
        float f0 = exp2f(m0 - nm0), f1 = exp2f(m1 - nm1);
        m0 = nm0; m1 = nm1;
        float s0 = 0.f, s1 = 0.f;
        #pragma unroll
        for (int j = 0; j < 8; j++) {
            sacc[j][0] = exp2f(sacc[j][0] - nm0); s0 += sacc[j][0];
            sacc[j][1] = exp2f(sacc[j][1] - nm0); s0 += sacc[j][1];
            sacc[j][2] = exp2f(sacc[j][2] - nm1); s1 += sacc[j][2];
            sacc[j][3] = exp2f(sacc[j][3] - nm1); s1 += sacc[j][3];
        }
        s0 += __shfl_xor_sync(0xffffffffu, s0, 1);
        s0 += __shfl_xor_sync(0xffffffffu, s0, 2);
        s1 += __shfl_xor_sync(0xffffffffu, s1, 1);
        s1 += __shfl_xor_sync(0xffffffffu, s1, 2);
        l0 = l0 * f0 + s0;
        l1 = l1 * f1 + s1;
        #pragma unroll
        for (int j = 0; j < 8; j++) {
            o[j][0] *= f0; o[j][1] *= f0;
            o[j][2] *= f1; o[j][3] *= f1;
        }

        // ---- O += P * V (identity relayout; P split hi/lo) ----
        #pragma unroll
        for (int c = 0; c < 4; c++) {
            uint4 ph, pl;
            ph.x = pksplit(sacc[2 * c][0],     sacc[2 * c][1],     &pl.x);
            ph.y = pksplit(sacc[2 * c][2],     sacc[2 * c][3],     &pl.y);
            ph.z = pksplit(sacc[2 * c + 1][0], sacc[2 * c + 1][1], &pl.z);
            ph.w = pksplit(sacc[2 * c + 1][2], sacc[2 * c + 1][3], &pl.w);
            #pragma unroll
            for (int j = 0; j < 8; j++) {
                uint2 vbf = *(const uint2*)&Vs[c][j][lane][0];
                mmabf(o[j], pl, vbf);
                mmabf(o[j], ph, vbf);
            }
        }
        __syncthreads();
    }

    // ---- finalize: bf16 hi/lo [B,S,H] for the out-projection ----
    int b = bh >> 4, h = bh & 15;
    float inv0 = 1.0f / l0, inv1 = 1.0f / l1;
    int r0 = qrow0 + g, r1 = r0 + 8;
    #pragma unroll
    for (int j = 0; j < 8; j++) {
        int col = h * HD + 8 * j + 2 * t;
        uint32_t lo0, lo1;
        uint32_t hi0 = pksplit(o[j][0] * inv0, o[j][1] * inv0, &lo0);
        uint32_t hi1 = pksplit(o[j][2] * inv1, o[j][3] * inv1, &lo1);
        size_t i0 = ((size_t)(b * SEQ + r0)) * H + col;
        size_t i1 = ((size_t)(b * SEQ + r1)) * H + col;
        *(uint32_t*)&ath[i0] = hi0; *(uint32_t*)&atl[i0] = lo0;
        *(uint32_t*)&ath[i1] = hi1; *(uint32_t*)&atl[i1] = lo1;
    }
}

// ---------------------------------------------------------------------------
extern "C" void kernel_launch(void* const* d_in, const int* in_sizes, int n_in,
                              void* d_out, int out_size) {
    const float* x     = (const float*)d_in[0];
    const float* Wq    = (const float*)d_in[1];
    const float* Wk    = (const float*)d_in[2];
    const float* Wv    = (const float*)d_in[3];
    const float* Wo    = (const float*)d_in[4];
    const float* bo    = (const float*)d_in[5];
    const float* gamma = (const float*)d_in[6];
    const float* beta  = (const float*)d_in[7];
    float* out = (float*)d_out;

    __nv_bfloat16 *xnh, *xnl, *wh, *qh, *ql, *kh, *vh, *ath, *atl;
    cudaGetSymbolAddress((void**)&xnh, g_xnh);
    cudaGetSymbolAddress((void**)&xnl, g_xnl);
    cudaGetSymbolAddress((void**)&wh,  g_wh);
    cudaGetSymbolAddress((void**)&qh,  g_qh);
    cudaGetSymbolAddress((void**)&ql,  g_ql);
    cudaGetSymbolAddress((void**)&kh,  g_kh);
    cudaGetSymbolAddress((void**)&vh,  g_vh);
    cudaGetSymbolAddress((void**)&ath, g_ath);
    cudaGetSymbolAddress((void**)&atl, g_atl);

    // 1. LayerNorm -> bf16 hi/lo
    ln_kernel<<<ROWS, 256>>>(x, gamma, beta, xnh, xnl);

    // 2. Weights -> bf16 hi
    wsplit_kernel<<<4 * H * H / 4 / 256, 256>>>(Wq, Wk, Wv, Wo, wh);

    // 3. QKV projections
    gemm_bf16_kernel<<<dim3(ROWS / 128, H / 128, 3), 256>>>(
        xnh, xnl, wh, qh, ql, kh, vh, nullptr, nullptr, nullptr, 0);

    // 4. Flash attention
    attn_bf16_kernel<<<dim3(SEQ / 128, BATCH * NH), 256>>>(qh, ql, kh, vh, ath, atl);

    // 5. Output projection + bias + residual
    gemm_bf16_kernel<<<dim3(ROWS / 128, H / 128, 1), 256>>>(
        ath, atl, wh + 3 * H * H, nullptr, nullptr, nullptr, nullptr,
        out, bo, x, 1);
}